// round 12
// baseline (speedup 1.0000x reference)
#include <cuda_runtime.h>
#include <cuda_bf16.h>
#include <math.h>
#include <cstdint>

#define B 64
#define H 2048
#define D 512
#define HID 512
#define M_TOTAL (B*H)
#define MASK_FILL_F (-4294967295.0f)
#define NCLUSTERS 74
#define NTILES 512            // M-tiles of 256 rows (one cluster each)
#define NTHREADS 320

#if defined(__CUDA_ARCH_FEAT_SM103_ALL) || defined(__CUDA_ARCH_FEAT_SM100_ALL) || defined(__CUDA_ARCH_FEAT_SM101_ALL)
#define TC_OK 1
#else
#define TC_OK 0
#endif

#define SW128(o) ((o) ^ (((o) >> 3) & 0x70))

#if TC_OK
__device__ __forceinline__ uint32_t smem_to_u32(const void* p) {
    uint32_t a;
    asm("{ .reg .u64 t; cvta.to.shared.u64 t, %1; cvt.u32.u64 %0, t; }"
        : "=r"(a) : "l"(p));
    return a;
}
__device__ __forceinline__ uint32_t cluster_rank() {
    uint32_t r;
    asm("mov.u32 %0, %%cluster_ctarank;" : "=r"(r));
    return r;
}
#define TCGEN05_ALLOC_CG2(sa, n) \
    asm volatile("tcgen05.alloc.cta_group::2.sync.aligned.shared::cta.b32 [%0], %1;" \
                 :: "r"((uint32_t)(sa)), "r"((uint32_t)(n)) : "memory")
#define TCGEN05_DEALLOC_CG2(ta, n) \
    asm volatile("tcgen05.dealloc.cta_group::2.sync.aligned.b32 %0, %1;" :: "r"(ta), "r"((uint32_t)(n)))
#define TCGEN05_RELINQUISH_CG2() \
    asm volatile("tcgen05.relinquish_alloc_permit.cta_group::2.sync.aligned;")
#define TCGEN05_COMMIT_MC_CG2(mb, mask) \
    asm volatile("tcgen05.commit.cta_group::2.mbarrier::arrive::one.shared::cluster.multicast::cluster.b64 [%0], %1;" \
                 :: "r"((uint32_t)(mb)), "h"((uint16_t)(mask)) : "memory")
#define TCGEN05_WAIT_LD()  asm volatile("tcgen05.wait::ld.sync.aligned;" ::: "memory")
#define TCGEN05_FENCE_BEFORE() asm volatile("tcgen05.fence::before_thread_sync;" ::: "memory")
#define TCGEN05_FENCE_AFTER()  asm volatile("tcgen05.fence::after_thread_sync;" ::: "memory")
#define FENCE_ASYNC_SHARED() asm volatile("fence.proxy.async.shared::cta;" ::: "memory")
#define CLUSTER_SYNC() do { \
    asm volatile("barrier.cluster.arrive.aligned;" ::: "memory"); \
    asm volatile("barrier.cluster.wait.aligned;" ::: "memory"); } while (0)
#define MBARRIER_INIT(mb, cnt) \
    asm volatile("mbarrier.init.shared.b64 [%0], %1;" :: "r"((uint32_t)(mb)), "r"((uint32_t)(cnt)) : "memory")
#define MBARRIER_EXPECT_TX(mb, bytes) \
    asm volatile("mbarrier.arrive.expect_tx.shared.b64 _, [%0], %1;" \
                 :: "r"((uint32_t)(mb)), "r"((uint32_t)(bytes)) : "memory")
#define MBARRIER_ARRIVE_CLUSTER(addr, rank) \
    asm volatile("{\n\t.reg .b32 r;\n\tmapa.shared::cluster.u32 r, %0, %1;\n\t" \
        "mbarrier.arrive.shared::cluster.b64 _, [r];\n\t}" \
        :: "r"((uint32_t)(addr)), "r"((uint32_t)(rank)) : "memory")
#define CP_ASYNC_BULK(dst, src, bytes, mb) \
    asm volatile("cp.async.bulk.shared::cta.global.mbarrier::complete_tx::bytes " \
                 "[%0], [%1], %2, [%3];" \
                 :: "r"((uint32_t)(dst)), "l"(src), "r"((uint32_t)(bytes)), \
                    "r"((uint32_t)(mb)) : "memory")
#define MBARRIER_WAIT_PARITY(mb, ph) do { \
    uint32_t _mb = (uint32_t)(mb); uint32_t _ph = (uint32_t)(ph); uint32_t _done; \
    asm volatile("{\n\t.reg .pred p;\n\t" \
        "mbarrier.try_wait.parity.acquire.cta.shared::cta.b64 p, [%1], %2;\n\t" \
        "selp.b32 %0, 1, 0, p;\n\t}" : "=r"(_done) : "r"(_mb), "r"(_ph) : "memory"); \
    if (!_done) { \
        asm volatile("{\n\t.reg .pred P1;\n\t" \
            "WL_%=:\n\t" \
            "mbarrier.try_wait.parity.acquire.cta.shared::cta.b64 P1, [%0], %1, 0x989680;\n\t" \
            "@P1 bra.uni WD_%=;\n\t" \
            "bra.uni WL_%=;\n\t" \
            "WD_%=:\n\t}" :: "r"(_mb), "r"(_ph) : "memory"); \
    } } while (0)
#define MBARRIER_WAIT_PARITY_CLU(mb, ph) do { \
    uint32_t _mb = (uint32_t)(mb); uint32_t _ph = (uint32_t)(ph); uint32_t _done; \
    asm volatile("{\n\t.reg .pred p;\n\t" \
        "mbarrier.try_wait.parity.acquire.cluster.shared::cta.b64 p, [%1], %2;\n\t" \
        "selp.b32 %0, 1, 0, p;\n\t}" : "=r"(_done) : "r"(_mb), "r"(_ph) : "memory"); \
    if (!_done) { \
        asm volatile("{\n\t.reg .pred P1;\n\t" \
            "WL_%=:\n\t" \
            "mbarrier.try_wait.parity.acquire.cluster.shared::cta.b64 P1, [%0], %1, 0x989680;\n\t" \
            "@P1 bra.uni WD_%=;\n\t" \
            "bra.uni WL_%=;\n\t" \
            "WD_%=:\n\t}" :: "r"(_mb), "r"(_ph) : "memory"); \
    } } while (0)
#define TCGEN05_LD_32X32B_X32(r, ta) \
    asm volatile("tcgen05.ld.sync.aligned.32x32b.x32.b32 " \
        "{%0, %1, %2, %3, %4, %5, %6, %7, %8, %9, %10, %11, %12, %13, %14, %15, " \
        " %16, %17, %18, %19, %20, %21, %22, %23, %24, %25, %26, %27, %28, %29, %30, %31}, [%32];" \
        : "=r"((r)[0]),  "=r"((r)[1]),  "=r"((r)[2]),  "=r"((r)[3]), \
          "=r"((r)[4]),  "=r"((r)[5]),  "=r"((r)[6]),  "=r"((r)[7]), \
          "=r"((r)[8]),  "=r"((r)[9]),  "=r"((r)[10]), "=r"((r)[11]), \
          "=r"((r)[12]), "=r"((r)[13]), "=r"((r)[14]), "=r"((r)[15]), \
          "=r"((r)[16]), "=r"((r)[17]), "=r"((r)[18]), "=r"((r)[19]), \
          "=r"((r)[20]), "=r"((r)[21]), "=r"((r)[22]), "=r"((r)[23]), \
          "=r"((r)[24]), "=r"((r)[25]), "=r"((r)[26]), "=r"((r)[27]), \
          "=r"((r)[28]), "=r"((r)[29]), "=r"((r)[30]), "=r"((r)[31]) \
        : "r"(ta))

static constexpr uint64_t SMEM_DESC_BASE_SW128 =
    (uint64_t(2)  << 61) | (uint64_t(1) << 46) | (uint64_t(64) << 32) | (uint64_t(1) << 16);
#define MAKE_SMEM_DESC(a) (SMEM_DESC_BASE_SW128 | ((uint64_t)((a) >> 4) & 0x3FFF))

// idesc kind::f16 cg2: dtype=F32, a/b=BF16, N=256, M=256
static constexpr uint32_t IDESC_BF16_CG2 =
    (1u << 4) | (1u << 7) | (1u << 10) | ((256u / 8) << 17) | ((256u / 16) << 24);

__device__ __forceinline__ void mma_bf16_ss_cg2(uint32_t d, uint64_t ad, uint64_t bd,
                                                uint32_t idesc, unsigned en) {
    asm volatile("{\n\t.reg .pred p;\n\tsetp.ne.u32 p, %5, 0;\n\t"
        "tcgen05.mma.cta_group::2.kind::f16 [%0], %1, %2, %3, "
        "{%4, %4, %4, %4, %4, %4, %4, %4}, p;\n\t}"
        :: "r"(d), "l"(ad), "l"(bd), "r"(idesc), "r"(0u), "r"(en) : "memory");
}
#endif // TC_OK

// ---------------------------------------------------------------------------
// Scratch
// ---------------------------------------------------------------------------
__device__ float    g_gate[B*D];
__device__ float    g_score[B*H];
__device__ __align__(16) unsigned char g_w1s[8*65536];   // bf16 w1^T SW128 images
__device__ int      g_flag_gt1 = 0;
__device__ int      g_flag_other = 0;

// ---------------------------------------------------------------------------
// Kernel S: merged setup — cvt_w1 / gate+zero-out / mask-dtype detect
// ---------------------------------------------------------------------------
__global__ void k_setup(const float* __restrict__ Kmat,
                        const float* __restrict__ W,
                        const float* __restrict__ w1,
                        const unsigned char* __restrict__ mask,
                        float* __restrict__ out) {
    const int blk = blockIdx.x;
    const int tid = threadIdx.x;
    if (blk < 128) {
        int lin = blk * 256 + tid;
        int n     = lin & 511;
        int kq    = (lin >> 9) & 7;
        int chunk = lin >> 12;
        int k0 = chunk*64 + kq*8;
        __nv_bfloat162 t[4];
        #pragma unroll
        for (int j = 0; j < 4; j++) {
            float f0 = w1[(k0 + 2*j    ) * HID + n];
            float f1 = w1[(k0 + 2*j + 1) * HID + n];
            t[j] = __floats2bfloat162_rn(f0, f1);
        }
        uint32_t off = (uint32_t)(n*128 + kq*16);
        *reinterpret_cast<uint4*>(g_w1s + chunk*65536 + SW128(off)) =
            *reinterpret_cast<uint4*>(t);
    } else if (blk < 256) {
        int i = (blk - 128) * 256 + tid;
        int k = i & 511;
        g_gate[i] = W[k*D + k] * Kmat[i];
        out[i] = 0.0f;
    } else {
        int lgt1 = 0, lother = 0;
        int base = (blk - 256) * 2048;
        for (int j = tid; j < 2048; j += 256) {
            int i = base + j;
            unsigned char v = mask[i];
            if (v > 1) lgt1 = 1;
            if (v != 0 && (i & 3) != 0) lother = 1;
        }
        if (__syncthreads_or(lgt1))   { if (tid == 0) atomicOr(&g_flag_gt1, 1); }
        if (__syncthreads_or(lother)) { if (tid == 0) atomicOr(&g_flag_other, 1); }
    }
}

// ---------------------------------------------------------------------------
// Kernel 1: persistent warp-specialized cg2 GEMM + overlapped epilogue.
//   Warps 0-3: epilogue; 4-7: A convert; 8: B loader; 9: MMA issuer (rank0).
//   TRDY and MDONE are 4-deep rings: the dependency chain bounds any
//   producer at <=3 steps ahead of its consumer, so 4 slots guarantee <=1
//   unconsumed flip per slot (2-slot rings alias parity -> R10/R11 hangs).
// ---------------------------------------------------------------------------
// SMEM map:
#define OFF_TMEM    0
#define MB_MDONE(b) (8  + (b)*8)            // 8,16,24,32   (count=1)
#define MB_BRDY(b)  (40 + (b)*8)            // 40,48,56     (count=1)
#define MB_TRDY(b)  (64 + (b)*8)            // 64,72,80,88  (rank0, count=2)
#define MB_NH0D     96
#define MB_NH1D     104
#define MB_EPI0     112                      // rank0, count=2
#define MB_EPI1     120                      // rank0, count=2
#define OFF_BIAS    128                      // 512 f32
#define OFF_W2V     2176                     // 512 f32
#define OFF_GS      4224                     // 512 f32
#define OFF_A(k)    (9216  + (k)*16384)      // 8 x 16 KB bf16 A (SW128)
#define OFF_B(s)    (140288 + (s)*16384)     // 3 x 16 KB bf16 B (SW128)
#define SMEM_BYTES  189440

__global__ __launch_bounds__(NTHREADS, 1) __cluster_dims__(2, 1, 1)
void k_gemm_tc(
        const float* __restrict__ V,
        const float* __restrict__ w1,
        const float* __restrict__ b1,
        const float* __restrict__ w2) {
    extern __shared__ char smem[];
    const int tid = threadIdx.x;

#if TC_OK
    const uint32_t sb = smem_to_u32(smem);
    const int wid = tid >> 5;
    const int lid = tid & 31;
    const uint32_t rank = cluster_rank();
    const int cid = blockIdx.x >> 1;

    float* bias = (float*)(smem + OFF_BIAS);
    float* w2s  = (float*)(smem + OFF_W2V);
    float* gs   = (float*)(smem + OFF_GS);
    for (int i = tid; i < D; i += NTHREADS) { bias[i] = b1[i]; w2s[i] = w2[i]; }

    if (wid == 0) TCGEN05_ALLOC_CG2(sb + OFF_TMEM, 512);
    if (tid == 0) {
        #pragma unroll
        for (int b = 0; b < 4; b++) MBARRIER_INIT(sb + MB_MDONE(b), 1);
        #pragma unroll
        for (int b = 0; b < 3; b++) MBARRIER_INIT(sb + MB_BRDY(b), 1);
        #pragma unroll
        for (int b = 0; b < 4; b++) MBARRIER_INIT(sb + MB_TRDY(b), 2);
        MBARRIER_INIT(sb + MB_NH0D, 1);     MBARRIER_INIT(sb + MB_NH1D, 1);
        MBARRIER_INIT(sb + MB_EPI0, 2);     MBARRIER_INIT(sb + MB_EPI1, 2);
    }
    __syncthreads();
    CLUSTER_SYNC();

    uint32_t tmem;
    asm volatile("ld.shared.b32 %0, [%1];" : "=r"(tmem) : "r"(sb + OFF_TMEM));

    // ====================== ROLE: warp 8 — B loader (both CTAs) =============
    if (wid == 8) {
        if (lid == 0) {
            int s3 = 0;                 // B slot (mod 3)
            int mdp[4] = {0, 0, 0, 0};  // MDONE parities (4-slot ring)
            long long gstep = 0;        // load counter; wait #w = gstep-3
            for (int t = cid; t < NTILES; t += NCLUSTERS) {
                for (int g = 0; g < 16; g++) {
                    if (gstep >= 3) {
                        int slot = (int)((gstep - 3) & 3);
                        MBARRIER_WAIT_PARITY(sb + MB_MDONE(slot), mdp[slot]);
                        mdp[slot] ^= 1;
                    }
                    int k  = g & 7;
                    int nh = g >> 3;
                    MBARRIER_EXPECT_TX(sb + MB_BRDY(s3), 16384u);
                    const unsigned char* src =
                        g_w1s + k*65536 + nh*32768 + rank*16384;
                    CP_ASYNC_BULK(sb + OFF_B(s3), (const void*)src, 16384u,
                                  sb + MB_BRDY(s3));
                    s3++; s3 -= (s3 >= 3) ? 3 : 0;
                    gstep++;
                }
            }
        }
    }
    // ====================== ROLE: warp 9 — MMA issuer (rank0) ===============
    else if (wid == 9) {
        if (lid == 0 && rank == 0) {
            int trp[4] = {0, 0, 0, 0};
            int s3 = 0;
            int ep0p = 0, ep1p = 0;
            bool first = true;
            for (int t = cid; t < NTILES; t += NCLUSTERS) {
                #pragma unroll 1
                for (int nh = 0; nh < 2; nh++) {
                    if (!first) {
                        if (nh == 0) { MBARRIER_WAIT_PARITY_CLU(sb + MB_EPI0, ep0p); ep0p ^= 1; }
                        else         { MBARRIER_WAIT_PARITY_CLU(sb + MB_EPI1, ep1p); ep1p ^= 1; }
                    }
                    uint32_t dbase = tmem + nh*256;
                    #pragma unroll 1
                    for (int k = 0; k < 8; k++) {
                        int s = nh*8 + k;          // step within tile
                        int slot = s & 3;
                        MBARRIER_WAIT_PARITY_CLU(sb + MB_TRDY(slot), trp[slot]);
                        trp[slot] ^= 1;
                        uint64_t ad = MAKE_SMEM_DESC(sb + OFF_A(k));
                        uint64_t bd = MAKE_SMEM_DESC(sb + OFF_B(s3));
                        #pragma unroll
                        for (int ks = 0; ks < 4; ks++) {
                            unsigned en = (k > 0 || ks > 0) ? 1u : 0u;
                            mma_bf16_ss_cg2(dbase, ad + ks*2, bd + ks*2,
                                            IDESC_BF16_CG2, en);
                        }
                        TCGEN05_COMMIT_MC_CG2(sb + MB_MDONE(slot), 0x3);
                        if (k == 7)
                            TCGEN05_COMMIT_MC_CG2(sb + (nh ? MB_NH1D : MB_NH0D), 0x3);
                        s3++; s3 -= (s3 >= 3) ? 3 : 0;
                    }
                }
                first = false;
            }
        }
    }
    // ====================== ROLE: warps 4-7 — convert =======================
    else if (wid >= 4) {
        const int idx = tid - 128;         // 0..127
        const int kq  = idx & 7;           // 8-float unit in row
        const int mb_ = idx >> 3;          // 0..15, rows mb_+l*16
        int nh1p = 0;
        int brp[3] = {0, 0, 0};
        int s3sig = 0;
        bool first = true;

        for (int t = cid; t < NTILES; t += NCLUSTERS) {
            const int row0 = t*256 + rank*128;
            const int b = row0 >> 11;
            const float* Vbase = V + (long long)row0 * D;

            if (!first) {                    // A region reuse gate
                MBARRIER_WAIT_PARITY(sb + MB_NH1D, nh1p);
                nh1p ^= 1;
            }
            // gate for this tile
            for (int i = idx; i < D; i += 128) gs[i] = g_gate[b*D + i];
            asm volatile("bar.sync 1, 128;" ::: "memory");

            float4 va[16], vb[16];
            // preload chunk 0
            #pragma unroll
            for (int l = 0; l < 8; l++) {
                const float* p = Vbase + (long long)(mb_ + l*16)*D + kq*8;
                va[2*l]   = *reinterpret_cast<const float4*>(p);
                va[2*l+1] = *reinterpret_cast<const float4*>(p + 4);
            }
            #pragma unroll 1
            for (int k = 0; k < 8; k++) {
                // prefetch chunk k+1
                if (k < 7) {
                    #pragma unroll
                    for (int l = 0; l < 8; l++) {
                        const float* p = Vbase + (long long)(mb_ + l*16)*D + (k+1)*64 + kq*8;
                        vb[2*l]   = *reinterpret_cast<const float4*>(p);
                        vb[2*l+1] = *reinterpret_cast<const float4*>(p + 4);
                    }
                }
                const float* gp = gs + k*64 + kq*8;
                float4 gA = *reinterpret_cast<const float4*>(gp);
                float4 gB = *reinterpret_cast<const float4*>(gp + 4);
                #pragma unroll
                for (int l = 0; l < 8; l++) {
                    int m = mb_ + l*16;
                    float4 v0 = va[2*l], v1 = va[2*l+1];
                    __nv_bfloat162 tt[4];
                    tt[0] = __floats2bfloat162_rn(v0.x*gA.x, v0.y*gA.y);
                    tt[1] = __floats2bfloat162_rn(v0.z*gA.z, v0.w*gA.w);
                    tt[2] = __floats2bfloat162_rn(v1.x*gB.x, v1.y*gB.y);
                    tt[3] = __floats2bfloat162_rn(v1.z*gB.z, v1.w*gB.w);
                    uint32_t off = (uint32_t)(m*128 + kq*16);
                    *reinterpret_cast<uint4*>(smem + OFF_A(k) + SW128(off)) =
                        *reinterpret_cast<uint4*>(tt);
                }
                FENCE_ASYNC_SHARED();
                asm volatile("bar.sync 1, 128;" ::: "memory");
                // signal thread: B ready + A[k] visible -> TRDY slot (k&3)
                if (idx == 0) {
                    MBARRIER_WAIT_PARITY(sb + MB_BRDY(s3sig), brp[s3sig]);
                    brp[s3sig] ^= 1;
                    s3sig++; s3sig -= (s3sig >= 3) ? 3 : 0;
                    MBARRIER_ARRIVE_CLUSTER(sb + MB_TRDY(k & 3), 0);
                }
                #pragma unroll
                for (int q = 0; q < 16; q++) va[q] = vb[q];
            }
            // nh1 signals (steps 8..15) — A already resident
            if (idx == 0) {
                #pragma unroll 1
                for (int g = 8; g < 16; g++) {
                    MBARRIER_WAIT_PARITY(sb + MB_BRDY(s3sig), brp[s3sig]);
                    brp[s3sig] ^= 1;
                    s3sig++; s3sig -= (s3sig >= 3) ? 3 : 0;
                    MBARRIER_ARRIVE_CLUSTER(sb + MB_TRDY(g & 3), 0);
                }
            }
            first = false;
        }
    }
    // ====================== ROLE: warps 0-3 — epilogue ======================
    else {
        int p0 = 0, p1 = 0;
        for (int t = cid; t < NTILES; t += NCLUSTERS) {
            const int row0 = t*256 + rank*128;
            float s = 0.0f;
            // --- half 0: D cols 0-255 ---
            MBARRIER_WAIT_PARITY(sb + MB_NH0D, p0); p0 ^= 1;
            TCGEN05_FENCE_AFTER();
            #pragma unroll 1
            for (int c = 0; c < 256; c += 64) {
                uint32_t r0[32], r1[32];
                TCGEN05_LD_32X32B_X32(r0, tmem + c);
                TCGEN05_LD_32X32B_X32(r1, tmem + c + 32);
                TCGEN05_WAIT_LD();
                #pragma unroll
                for (int j = 0; j < 32; j++) {
                    float v0 = __uint_as_float(r0[j]) + bias[c + j];
                    float v1 = __uint_as_float(r1[j]) + bias[c + 32 + j];
                    s += fmaxf(v0, 0.0f) * w2s[c + j];
                    s += fmaxf(v1, 0.0f) * w2s[c + 32 + j];
                }
            }
            TCGEN05_FENCE_BEFORE();
            asm volatile("bar.sync 2, 128;" ::: "memory");
            if (tid == 0) MBARRIER_ARRIVE_CLUSTER(sb + MB_EPI0, 0);
            // --- half 1: D cols 256-511 ---
            MBARRIER_WAIT_PARITY(sb + MB_NH1D, p1); p1 ^= 1;
            TCGEN05_FENCE_AFTER();
            #pragma unroll 1
            for (int c = 0; c < 256; c += 64) {
                uint32_t r0[32], r1[32];
                TCGEN05_LD_32X32B_X32(r0, tmem + 256 + c);
                TCGEN05_LD_32X32B_X32(r1, tmem + 256 + c + 32);
                TCGEN05_WAIT_LD();
                #pragma unroll
                for (int j = 0; j < 32; j++) {
                    float v0 = __uint_as_float(r0[j]) + bias[256 + c + j];
                    float v1 = __uint_as_float(r1[j]) + bias[256 + c + 32 + j];
                    s += fmaxf(v0, 0.0f) * w2s[256 + c + j];
                    s += fmaxf(v1, 0.0f) * w2s[256 + c + 32 + j];
                }
            }
            TCGEN05_FENCE_BEFORE();
            g_score[row0 + wid*32 + lid] = s;
            asm volatile("bar.sync 2, 128;" ::: "memory");
            if (tid == 0) MBARRIER_ARRIVE_CLUSTER(sb + MB_EPI1, 0);
        }
    }

    __syncthreads();
    CLUSTER_SYNC();
    if (wid == 0) {
        TCGEN05_RELINQUISH_CG2();
        TCGEN05_DEALLOC_CG2(tmem, 512);
    }
#else
    // ================= simple correct fallback (never runs on GB300) =======
    for (long long r = blockIdx.x * NTHREADS + tid; r < M_TOTAL;
         r += (long long)gridDim.x * NTHREADS) {
        int b = (int)(r >> 11);
        const float* vrow = V + r * D;
        float s = 0.0f;
        for (int n = 0; n < HID; n++) {
            float x = 0.0f;
            for (int k = 0; k < D; k++)
                x = fmaf(vrow[k] * g_gate[b*D + k], w1[k*HID + n], x);
            s += fmaxf(x + b1[n], 0.0f) * w2[n];
        }
        g_score[r] = s;
    }
#endif
}

// ---------------------------------------------------------------------------
// Kernel 2: masked softmax over h per batch, alpha stored in place
// ---------------------------------------------------------------------------
__global__ __launch_bounds__(256) void k_softmax(const void* __restrict__ mask_raw) {
    const int b   = blockIdx.x;
    const int tid = threadIdx.x;
    __shared__ float sh[256];

    const int mode = g_flag_gt1 ? 2 : (g_flag_other ? 0 : 1);
    const unsigned char* m8  = (const unsigned char*)mask_raw;
    const int*           m32 = (const int*)mask_raw;
    const float*         mf  = (const float*)mask_raw;

    float s[8];
    float mx = -3.0e38f;
    #pragma unroll
    for (int l = 0; l < 8; l++) {
        int idx = b*H + tid + l*256;
        bool masked;
        if (mode == 1)      masked = (m32[idx] != 0);
        else if (mode == 2) masked = (mf[idx] != 0.0f);
        else                masked = (m8[idx] != 0);
        float v = g_score[idx];
        if (masked) v = MASK_FILL_F;
        s[l] = v;
        mx = fmaxf(mx, v);
    }
    sh[tid] = mx; __syncthreads();
    for (int off = 128; off > 0; off >>= 1) {
        if (tid < off) sh[tid] = fmaxf(sh[tid], sh[tid + off]);
        __syncthreads();
    }
    mx = sh[0];
    __syncthreads();

    float e[8], sum = 0.0f;
    #pragma unroll
    for (int l = 0; l < 8; l++) { e[l] = expf(s[l] - mx); sum += e[l]; }
    sh[tid] = sum; __syncthreads();
    for (int off = 128; off > 0; off >>= 1) {
        if (tid < off) sh[tid] += sh[tid + off];
        __syncthreads();
    }
    float inv = 1.0f / sh[0];
    #pragma unroll
    for (int l = 0; l < 8; l++) g_score[b*H + tid + l*256] = e[l] * inv;
}

// ---------------------------------------------------------------------------
// Kernel 3: attn[b,d] = sum_h alpha[b,h] * V[b,h,d]
// ---------------------------------------------------------------------------
__global__ __launch_bounds__(128) void k_wsum(const float* __restrict__ V,
                                              float* __restrict__ out) {
    const int b   = blockIdx.x;
    const int h0  = blockIdx.y * 64;
    const int tid = threadIdx.x;
    __shared__ float al[64];
    if (tid < 64) al[tid] = g_score[b*H + h0 + tid];
    __syncthreads();

    const float4* Vb = reinterpret_cast<const float4*>(
        V + ((long long)b*H + h0) * D);
    float4 acc = make_float4(0.f, 0.f, 0.f, 0.f);
    #pragma unroll 8
    for (int h = 0; h < 64; h++) {
        float a = al[h];
        float4 v = Vb[(long long)h*128 + tid];
        acc.x = fmaf(a, v.x, acc.x);
        acc.y = fmaf(a, v.y, acc.y);
        acc.z = fmaf(a, v.z, acc.z);
        acc.w = fmaf(a, v.w, acc.w);
    }
    float* o = out + b*D + tid*4;
    atomicAdd(o + 0, acc.x);
    atomicAdd(o + 1, acc.y);
    atomicAdd(o + 2, acc.z);
    atomicAdd(o + 3, acc.w);
}

// ---------------------------------------------------------------------------
extern "C" void kernel_launch(void* const* d_in, const int* in_sizes, int n_in,
                              void* d_out, int out_size) {
    const float* Kmat = (const float*)d_in[0];
    const float* V    = (const float*)d_in[1];
    const void*  mask = d_in[2];
    const float* W    = (const float*)d_in[3];
    const float* w1   = (const float*)d_in[4];
    const float* b1   = (const float*)d_in[5];
    const float* w2   = (const float*)d_in[6];
    // b2 is a uniform score shift -> softmax-invariant, unused.
    float* out = (float*)d_out;

    cudaFuncSetAttribute(k_gemm_tc, cudaFuncAttributeMaxDynamicSharedMemorySize,
                         SMEM_BYTES);

    k_setup<<<320, 256>>>(Kmat, W, w1, (const unsigned char*)mask, out);
    k_gemm_tc<<<NCLUSTERS*2, NTHREADS, SMEM_BYTES>>>(V, w1, b1, w2);
    k_softmax<<<B, 256>>>(mask);
    k_wsum<<<dim3(B, 32), 128>>>(V, out);
}